// round 2
// baseline (speedup 1.0000x reference)
#include <cuda_runtime.h>
#include <cstdint>

#define N_NODES 100000
#define N_EDGES 1600000
#define IN_DIM 128
#define OUT_DIM 64
#define NEG 0.2f
#define EPSV 1e-8f

// ---------------- scratch (device globals: allocation-free) ----------------
__device__ float g_Qr[(size_t)N_NODES * 256];   // leaky(Q), [node][h*64+d]
__device__ float g_Kr[(size_t)N_NODES * 256];   // leaky(K)
__device__ float g_Hb[(size_t)N_NODES * 256];   // H + bias
__device__ float g_e [(size_t)N_EDGES * 4];     // exp(score) per edge per head (CSR order)
__device__ int   g_ecol[N_EDGES];
__device__ int   g_deg [N_NODES];
__device__ int   g_rowptr[N_NODES + 1];
__device__ int   g_cursor[N_NODES];
__device__ int   g_is64;

// ---------------- f32x2 helpers ----------------
__device__ __forceinline__ void fma2(unsigned long long& d, unsigned long long a, unsigned long long b) {
    asm("fma.rn.f32x2 %0, %1, %2, %0;" : "+l"(d) : "l"(a), "l"(b));
}
__device__ __forceinline__ unsigned long long splat2(float a) {
    unsigned long long r;
    asm("mov.b64 %0, {%1, %1};" : "=l"(r) : "f"(a));
    return r;
}
__device__ __forceinline__ float2 unpack2(unsigned long long v) {
    float2 r;
    asm("mov.b64 {%0, %1}, %2;" : "=f"(r.x), "=f"(r.y) : "l"(v));
    return r;
}

// ---------------- dtype detection (int64 vs silently-int32 edge_index) -----
// If the buffer really is int64, every 8-byte word is a valid node id in [0,N).
// If it is int32 data misread as int64, a sampled word packs two int32 ids:
// (hi<<32)|lo >= N_NODES whenever hi != 0 (prob hi==0 is ~N/2^32 per sample).
__global__ void gat_detect(const void* __restrict__ ei, int E) {
    if (threadIdx.x == 0 && blockIdx.x == 0) {
        const long long* p = (const long long*)ei;
        const int stride = E / 16;   // sample spread across row 0
        int ok = 1;
        #pragma unroll
        for (int i = 0; i < 16; i++) {
            long long v = p[(size_t)i * stride];
            if (v < 0 || v >= (long long)N_NODES) ok = 0;
        }
        g_is64 = ok;
    }
}

__device__ __forceinline__ int load_idx(const void* __restrict__ ei, int pos) {
    if (g_is64) return (int)((const long long*)ei)[pos];
    return ((const int*)ei)[pos];
}

// ---------------- fused projection GEMM ----------------
// Conceptual C[768 x N]: y-tiles 0..5 -> matrix m=y/2 (0=Q,1=K,2=H), col base (y&1)*128
#define BM 128
#define BN 128
#define BK 16
#define LDAS (BM + 4)
#define LDBS (BN + 4)

__global__ __launch_bounds__(256) void gat_gemm(
    const float* __restrict__ x,
    const float* __restrict__ Wq, const float* __restrict__ Wk,
    const float* __restrict__ Wh, const float* __restrict__ bh, int n)
{
    __shared__ float As[BK * LDAS];
    __shared__ float Bs[BK * LDBS];

    const int m0  = blockIdx.x * BM;
    const int mtx = blockIdx.y >> 1;           // 0=Q, 1=K, 2=H
    const int j0  = (blockIdx.y & 1) * BN;     // column base within [0,256)
    const float* __restrict__ W = (mtx == 0) ? Wq : ((mtx == 1) ? Wk : Wh);

    const int tid = threadIdx.x;
    const int tr = tid >> 4;      // 0..15 -> rows tr*8..+8
    const int tc = tid & 15;      // 0..15 -> cols tc*8..+8

    const int lrow = tid >> 2;          // 0..63 (load row helper)
    const int lk   = (tid & 3) * 4;     // 0,4,8,12

    unsigned long long acc[8][4];
    #pragma unroll
    for (int i = 0; i < 8; i++)
        #pragma unroll
        for (int j = 0; j < 4; j++) acc[i][j] = 0ULL;

    for (int kc = 0; kc < IN_DIM; kc += BK) {
        // global loads (A: 2 rows/thread, B: 2 rows/thread)
        const int r0 = m0 + lrow, r1 = r0 + 64;
        float4 a0 = make_float4(0.f, 0.f, 0.f, 0.f), a1 = a0;
        if (r0 < n) a0 = *(const float4*)(x + r0 * IN_DIM + kc + lk);
        if (r1 < n) a1 = *(const float4*)(x + r1 * IN_DIM + kc + lk);
        float4 b0 = *(const float4*)(W + (j0 + lrow)      * IN_DIM + kc + lk);
        float4 b1 = *(const float4*)(W + (j0 + lrow + 64) * IN_DIM + kc + lk);

        __syncthreads();
        As[(lk + 0) * LDAS + lrow] = a0.x;  As[(lk + 1) * LDAS + lrow] = a0.y;
        As[(lk + 2) * LDAS + lrow] = a0.z;  As[(lk + 3) * LDAS + lrow] = a0.w;
        As[(lk + 0) * LDAS + lrow + 64] = a1.x;  As[(lk + 1) * LDAS + lrow + 64] = a1.y;
        As[(lk + 2) * LDAS + lrow + 64] = a1.z;  As[(lk + 3) * LDAS + lrow + 64] = a1.w;
        Bs[(lk + 0) * LDBS + lrow] = b0.x;  Bs[(lk + 1) * LDBS + lrow] = b0.y;
        Bs[(lk + 2) * LDBS + lrow] = b0.z;  Bs[(lk + 3) * LDBS + lrow] = b0.w;
        Bs[(lk + 0) * LDBS + lrow + 64] = b1.x;  Bs[(lk + 1) * LDBS + lrow + 64] = b1.y;
        Bs[(lk + 2) * LDBS + lrow + 64] = b1.z;  Bs[(lk + 3) * LDBS + lrow + 64] = b1.w;
        __syncthreads();

        #pragma unroll
        for (int k = 0; k < BK; k++) {
            const float4 af0 = *(const float4*)&As[k * LDAS + tr * 8];
            const float4 af1 = *(const float4*)&As[k * LDAS + tr * 8 + 4];
            const unsigned long long* bp = (const unsigned long long*)&Bs[k * LDBS + tc * 8];
            unsigned long long bf0 = bp[0], bf1 = bp[1], bf2 = bp[2], bf3 = bp[3];
            float av[8] = {af0.x, af0.y, af0.z, af0.w, af1.x, af1.y, af1.z, af1.w};
            #pragma unroll
            for (int i = 0; i < 8; i++) {
                unsigned long long aa = splat2(av[i]);
                fma2(acc[i][0], aa, bf0);
                fma2(acc[i][1], aa, bf1);
                fma2(acc[i][2], aa, bf2);
                fma2(acc[i][3], aa, bf3);
            }
        }
    }

    // epilogue: leaky-relu (Q,K) or +bias (H), write [node][256] layout
    float* __restrict__ dst = (mtx == 0) ? g_Qr : ((mtx == 1) ? g_Kr : g_Hb);
    const int cbase = j0 + tc * 8;
    float bias[8];
    if (mtx == 2) {
        #pragma unroll
        for (int j = 0; j < 8; j++) bias[j] = bh[cbase + j];
    }
    #pragma unroll
    for (int i = 0; i < 8; i++) {
        const int row = m0 + tr * 8 + i;
        if (row >= n) continue;
        float* __restrict__ drow = dst + row * 256 + cbase;
        #pragma unroll
        for (int j = 0; j < 4; j++) {
            float2 v = unpack2(acc[i][j]);
            if (mtx < 2) {
                v.x = v.x > 0.f ? v.x : NEG * v.x;
                v.y = v.y > 0.f ? v.y : NEG * v.y;
            } else {
                v.x += bias[2 * j];
                v.y += bias[2 * j + 1];
            }
            *(float2*)(drow + 2 * j) = v;
        }
    }
}

// ---------------- CSR build ----------------
__global__ void gat_zero(int n) {
    int i = blockIdx.x * blockDim.x + threadIdx.x;
    if (i < n) g_deg[i] = 0;
}

__global__ void gat_deg(const void* __restrict__ ei, int E) {
    int e = blockIdx.x * blockDim.x + threadIdx.x;
    if (e < E) atomicAdd(&g_deg[load_idx(ei, e)], 1);
}

// single-block exclusive scan, warp-shuffle based (1024 threads = 32 warps)
__global__ void gat_scan(int n) {
    __shared__ int warpsum[32];
    const int tid  = threadIdx.x;
    const int lane = tid & 31;
    const int wid  = tid >> 5;
    int carry = 0;
    for (int base = 0; base < n; base += 1024) {
        const int i = base + tid;
        const int v = (i < n) ? g_deg[i] : 0;
        // inclusive scan within warp
        int s = v;
        #pragma unroll
        for (int off = 1; off < 32; off <<= 1) {
            int t = __shfl_up_sync(0xFFFFFFFFu, s, off);
            if (lane >= off) s += t;
        }
        if (lane == 31) warpsum[wid] = s;
        __syncthreads();
        if (wid == 0) {
            int w = warpsum[lane];
            #pragma unroll
            for (int off = 1; off < 32; off <<= 1) {
                int t = __shfl_up_sync(0xFFFFFFFFu, w, off);
                if (lane >= off) w += t;
            }
            warpsum[lane] = w;
        }
        __syncthreads();
        const int wbase = (wid == 0) ? 0 : warpsum[wid - 1];
        const int total = warpsum[31];
        if (i < n) {
            const int ex = carry + wbase + s - v;
            g_rowptr[i] = ex;
            g_cursor[i] = ex;
        }
        carry += total;
        __syncthreads();
    }
    if (tid == 0) g_rowptr[n] = carry;
}

__global__ void gat_scatter(const void* __restrict__ ei, int E) {
    int e = blockIdx.x * blockDim.x + threadIdx.x;
    if (e < E) {
        int r = load_idx(ei, e);
        int c = load_idx(ei, E + e);
        int p = atomicAdd(&g_cursor[r], 1);
        g_ecol[p] = c;
    }
}

// ---------------- per-node attention (warp per node) ----------------
// Row layout of Qr/Kr/Hb: 256 floats = [head0 64][head1 64][head2 64][head3 64]
// lane l: float4 index l -> head l/16 (0 or 1); float4 index l+32 -> head 2 + l/16
__global__ __launch_bounds__(256) void gat_node(float* __restrict__ out, int n) {
    const int warp = (blockIdx.x * blockDim.x + threadIdx.x) >> 5;
    const int lane = threadIdx.x & 31;
    if (warp >= n) return;
    const int u = warp;
    const int p0 = g_rowptr[u], p1 = g_rowptr[u + 1];

    const float4* __restrict__ qp = (const float4*)(g_Qr + (size_t)u * 256);
    const float4 q0 = qp[lane];
    const float4 q1 = qp[lane + 32];

    float z0 = 0.f, z1 = 0.f;

    for (int p = p0; p < p1; p++) {
        const int v = g_ecol[p];
        const float4* __restrict__ kp = (const float4*)(g_Kr + (size_t)v * 256);
        const float4 k0 = kp[lane];
        const float4 k1 = kp[lane + 32];
        float s0 = q0.x * k0.x + q0.y * k0.y + q0.z * k0.z + q0.w * k0.w;
        float s1 = q1.x * k1.x + q1.y * k1.y + q1.z * k1.z + q1.w * k1.w;
        #pragma unroll
        for (int off = 8; off; off >>= 1) {
            s0 += __shfl_xor_sync(0xFFFFFFFFu, s0, off);
            s1 += __shfl_xor_sync(0xFFFFFFFFu, s1, off);
        }
        // lanes 0-15: (head0 in s0, head2 in s1); lanes 16-31: (head1, head3)
        float e0 = __expf(s0 * 0.125f);
        float e1 = __expf(s1 * 0.125f);
        z0 += e0;
        z1 += e1;
        float eh1 = __shfl_sync(0xFFFFFFFFu, e0, 16);
        float eh3 = __shfl_sync(0xFFFFFFFFu, e1, 16);
        if (lane == 0)
            *(float4*)(g_e + 4 * (size_t)p) = make_float4(e0, eh1, e1, eh3);
    }

    const float zh0 = __shfl_sync(0xFFFFFFFFu, z0, 0);
    const float zh1 = __shfl_sync(0xFFFFFFFFu, z0, 16);
    const float zh2 = __shfl_sync(0xFFFFFFFFu, z1, 0);
    const float zh3 = __shfl_sync(0xFFFFFFFFu, z1, 16);
    const float i0 = 1.0f / (zh0 + EPSV);
    const float i1 = 1.0f / (zh1 + EPSV);
    const float i2 = 1.0f / (zh2 + EPSV);
    const float i3 = 1.0f / (zh3 + EPSV);

    float ax = 0.f, ay = 0.f;
    const int d2 = lane * 2;
    for (int p = p0; p < p1; p++) {
        const int v = g_ecol[p];
        const float4 ev = *(const float4*)(g_e + 4 * (size_t)p);
        const float a0 = ev.x * i0, a1 = ev.y * i1, a2 = ev.z * i2, a3 = ev.w * i3;
        const float* __restrict__ hb = g_Hb + (size_t)v * 256 + d2;
        const float2 h0 = *(const float2*)(hb);
        const float2 h1 = *(const float2*)(hb + 64);
        const float2 h2 = *(const float2*)(hb + 128);
        const float2 h3 = *(const float2*)(hb + 192);
        ax += a0 * h0.x + a1 * h1.x + a2 * h2.x + a3 * h3.x;
        ay += a0 * h0.y + a1 * h1.y + a2 * h2.y + a3 * h3.y;
    }
    *(float2*)(out + (size_t)u * 64 + d2) = make_float2(ax * 0.25f, ay * 0.25f);
}

// ---------------- launch ----------------
extern "C" void kernel_launch(void* const* d_in, const int* in_sizes, int n_in,
                              void* d_out, int out_size) {
    const float* x  = (const float*)d_in[0];
    const void*  ei = d_in[1];
    const float* Wq = (const float*)d_in[2];
    const float* Wk = (const float*)d_in[3];
    const float* Wh = (const float*)d_in[4];
    const float* bh = (const float*)d_in[5];
    float* out = (float*)d_out;

    const int n = in_sizes[0] / IN_DIM;
    const int E = in_sizes[1] / 2;

    gat_detect<<<1, 32>>>(ei, E);

    dim3 gg((n + BM - 1) / BM, 6);
    gat_gemm<<<gg, 256>>>(x, Wq, Wk, Wh, bh, n);

    gat_zero<<<(n + 255) / 256, 256>>>(n);
    gat_deg<<<(E + 255) / 256, 256>>>(ei, E);
    gat_scan<<<1, 1024>>>(n);
    gat_scatter<<<(E + 255) / 256, 256>>>(ei, E);

    const int nblocks = (n * 32 + 255) / 256;
    gat_node<<<nblocks, 256>>>(out, n);
}

// round 4
// speedup vs baseline: 1.5530x; 1.5530x over previous
#include <cuda_runtime.h>
#include <cstdint>

#define N_NODES 100000
#define N_EDGES 1600000
#define IN_DIM 128
#define OUT_DIM 64
#define NEG 0.2f
#define EPSV 1e-8f

// ---------------- scratch (device globals: allocation-free) ----------------
__device__ float g_Qr[(size_t)N_NODES * 256];   // leaky(Q), [node][h*64+d]
__device__ float g_Kr[(size_t)N_NODES * 256];   // leaky(K)
__device__ float g_Hb[(size_t)N_NODES * 256];   // H + bias
__device__ float g_Wt[(size_t)3 * 128 * 256];   // W transposed: [mtx][k][n]
__device__ float g_e [(size_t)N_EDGES * 4];     // exp(score) per edge per head (CSR order)
__device__ float g_zinv[(size_t)N_NODES * 4];   // 1/(z+eps) per node per head
__device__ int   g_ecol[N_EDGES];
__device__ int   g_deg [N_NODES];
__device__ int   g_rowptr[N_NODES + 1];
__device__ int   g_cursor[N_NODES];
__device__ int   g_is64;

// ---------------- helpers ----------------
__device__ __forceinline__ uint32_t to_tf32(float x) {
    uint32_t r;
    asm("cvt.rna.tf32.f32 %0, %1;" : "=r"(r) : "f"(x));
    return r;
}
__device__ __forceinline__ void mma_tf32(float* d, const uint32_t* a, uint32_t b0, uint32_t b1) {
    asm volatile(
        "mma.sync.aligned.m16n8k8.row.col.f32.tf32.tf32.f32 "
        "{%0,%1,%2,%3}, {%4,%5,%6,%7}, {%8,%9}, {%0,%1,%2,%3};"
        : "+f"(d[0]), "+f"(d[1]), "+f"(d[2]), "+f"(d[3])
        : "r"(a[0]), "r"(a[1]), "r"(a[2]), "r"(a[3]), "r"(b0), "r"(b1));
}

// ---------------- dtype detection (int64 vs silently-int32 edge_index) -----
__global__ void gat_detect(const void* __restrict__ ei, int E) {
    if (threadIdx.x == 0 && blockIdx.x == 0) {
        const long long* p = (const long long*)ei;
        const int stride = E / 16;
        int ok = 1;
        #pragma unroll
        for (int i = 0; i < 16; i++) {
            long long v = p[(size_t)i * stride];
            if (v < 0 || v >= (long long)N_NODES) ok = 0;
        }
        g_is64 = ok;
    }
}

__device__ __forceinline__ int load_idx(const void* __restrict__ ei, int pos) {
    if (g_is64) return (int)((const long long*)ei)[pos];
    return ((const int*)ei)[pos];
}

// ---------------- W transpose: [n][k] -> [k][n] (k-major for B fills) ------
__global__ void gat_wt(const float* __restrict__ Wq, const float* __restrict__ Wk,
                       const float* __restrict__ Wh) {
    const float* __restrict__ W = (blockIdx.x == 0) ? Wq : ((blockIdx.x == 1) ? Wk : Wh);
    float* __restrict__ dst = g_Wt + (size_t)blockIdx.x * 128 * 256;
    for (int i = threadIdx.x; i < 256 * 128; i += blockDim.x) {
        const int nrow = i >> 7;        // 0..255
        const int k    = i & 127;       // 0..127
        dst[k * 256 + nrow] = W[i];     // coalesced read, scattered write (tiny)
    }
}

// ---------------- mma.sync tf32 projection GEMM ----------------
// CTA tile: 64 rows x 256 cols, K=128 chunked by 32.
// 8 warps: warp (wid>>2) -> row group *32, (wid&3) -> col group *64.
// Warp tile 32x64 = 2 m-atoms x 8 n-atoms of m16n8k8.
#define BM 64
#define BK 32
#define LDA 36      // As[m][k]: bank = (4*row + k) % 32  -> conflict-free frags
#define LDB 264     // Bs[k][n]: bank = (8*k + n) % 32    -> conflict-free frags

__global__ __launch_bounds__(256) void gat_gemm(
    const float* __restrict__ x, const float* __restrict__ bh, int n)
{
    __shared__ float As[BM * LDA];
    __shared__ float Bs[BK * LDB];

    const int tid  = threadIdx.x;
    const int wid  = tid >> 5;
    const int lane = tid & 31;
    const int m0   = blockIdx.x * BM;
    const int mtx  = blockIdx.y;                 // 0=Q, 1=K, 2=H
    const float* __restrict__ Wt = g_Wt + (size_t)mtx * 128 * 256;

    const int wr = (wid >> 2) * 32;              // warp row base in tile
    const int wc = (wid & 3) * 64;               // warp col base in tile
    const int lr = lane >> 2;                    // 0..7
    const int lc = lane & 3;                     // 0..3

    float acc[2][8][4];
    #pragma unroll
    for (int i = 0; i < 2; i++)
        #pragma unroll
        for (int j = 0; j < 8; j++)
            #pragma unroll
            for (int t = 0; t < 4; t++) acc[i][j][t] = 0.f;

    for (int kc = 0; kc < IN_DIM; kc += BK) {
        // fill A: 64 rows x 32 k (tf32-rounded)
        #pragma unroll
        for (int i = tid; i < 512; i += 256) {
            const int row = i >> 3;
            const int kq  = (i & 7) * 4;
            const int grow = m0 + row;
            float4 v = make_float4(0.f, 0.f, 0.f, 0.f);
            if (grow < n) v = *(const float4*)(x + (size_t)grow * IN_DIM + kc + kq);
            uint4 t;
            t.x = to_tf32(v.x); t.y = to_tf32(v.y); t.z = to_tf32(v.z); t.w = to_tf32(v.w);
            *(uint4*)&As[row * LDA + kq] = t;
        }
        // fill B: 32 k x 256 n from Wt (already k-major: direct copy)
        #pragma unroll
        for (int i = tid; i < 2048; i += 256) {
            const int k  = i >> 6;
            const int nq = (i & 63) * 4;
            float4 v = *(const float4*)(Wt + (size_t)(kc + k) * 256 + nq);
            uint4 t;
            t.x = to_tf32(v.x); t.y = to_tf32(v.y); t.z = to_tf32(v.z); t.w = to_tf32(v.w);
            *(uint4*)&Bs[k * LDB + nq] = t;
        }
        __syncthreads();

        #pragma unroll
        for (int ks = 0; ks < 4; ks++) {
            uint32_t a[2][4];
            #pragma unroll
            for (int i = 0; i < 2; i++) {
                const float* ap = &As[(wr + i * 16 + lr) * LDA + ks * 8 + lc];
                a[i][0] = __float_as_uint(ap[0]);
                a[i][1] = __float_as_uint(ap[8 * LDA]);
                a[i][2] = __float_as_uint(ap[4]);
                a[i][3] = __float_as_uint(ap[8 * LDA + 4]);
            }
            #pragma unroll
            for (int j = 0; j < 8; j++) {
                const float* bp = &Bs[(ks * 8 + lc) * LDB + wc + j * 8 + lr];
                const uint32_t b0 = __float_as_uint(bp[0]);
                const uint32_t b1 = __float_as_uint(bp[4 * LDB]);
                mma_tf32(acc[0][j], a[0], b0, b1);
                mma_tf32(acc[1][j], a[1], b0, b1);
            }
        }
        __syncthreads();
    }

    // epilogue: leaky-relu (Q,K) or +bias (H); dst layout [node][256]
    float* __restrict__ dst = (mtx == 0) ? g_Qr : ((mtx == 1) ? g_Kr : g_Hb);
    #pragma unroll
    for (int i = 0; i < 2; i++) {
        const int r0 = m0 + wr + i * 16 + lr;    // accum row for c0/c1
        const int r1 = r0 + 8;                   // accum row for c2/c3
        #pragma unroll
        for (int j = 0; j < 8; j++) {
            const int col = wc + j * 8 + lc * 2;
            float2 v0 = make_float2(acc[i][j][0], acc[i][j][1]);
            float2 v1 = make_float2(acc[i][j][2], acc[i][j][3]);
            if (mtx < 2) {
                v0.x = v0.x > 0.f ? v0.x : NEG * v0.x;
                v0.y = v0.y > 0.f ? v0.y : NEG * v0.y;
                v1.x = v1.x > 0.f ? v1.x : NEG * v1.x;
                v1.y = v1.y > 0.f ? v1.y : NEG * v1.y;
            } else {
                const float bx = bh[col], by = bh[col + 1];
                v0.x += bx; v0.y += by;
                v1.x += bx; v1.y += by;
            }
            if (r0 < n) *(float2*)(dst + (size_t)r0 * 256 + col) = v0;
            if (r1 < n) *(float2*)(dst + (size_t)r1 * 256 + col) = v1;
        }
    }
}

// ---------------- CSR build ----------------
__global__ void gat_zero(int n) {
    int i = blockIdx.x * blockDim.x + threadIdx.x;
    if (i < n) g_deg[i] = 0;
}

__global__ void gat_deg(const void* __restrict__ ei, int E) {
    int e = blockIdx.x * blockDim.x + threadIdx.x;
    if (e < E) atomicAdd(&g_deg[load_idx(ei, e)], 1);
}

// single-block exclusive scan, warp-shuffle based (1024 threads = 32 warps)
__global__ void gat_scan(int n) {
    __shared__ int warpsum[32];
    const int tid  = threadIdx.x;
    const int lane = tid & 31;
    const int wid  = tid >> 5;
    int carry = 0;
    for (int base = 0; base < n; base += 1024) {
        const int i = base + tid;
        const int v = (i < n) ? g_deg[i] : 0;
        int s = v;
        #pragma unroll
        for (int off = 1; off < 32; off <<= 1) {
            int t = __shfl_up_sync(0xFFFFFFFFu, s, off);
            if (lane >= off) s += t;
        }
        if (lane == 31) warpsum[wid] = s;
        __syncthreads();
        if (wid == 0) {
            int w = warpsum[lane];
            #pragma unroll
            for (int off = 1; off < 32; off <<= 1) {
                int t = __shfl_up_sync(0xFFFFFFFFu, w, off);
                if (lane >= off) w += t;
            }
            warpsum[lane] = w;
        }
        __syncthreads();
        const int wbase = (wid == 0) ? 0 : warpsum[wid - 1];
        const int total = warpsum[31];
        if (i < n) {
            const int ex = carry + wbase + s - v;
            g_rowptr[i] = ex;
            g_cursor[i] = ex;
        }
        carry += total;
        __syncthreads();
    }
    if (tid == 0) g_rowptr[n] = carry;
}

__global__ void gat_scatter(const void* __restrict__ ei, int E) {
    int e = blockIdx.x * blockDim.x + threadIdx.x;
    if (e < E) {
        int r = load_idx(ei, e);
        int c = load_idx(ei, E + e);
        int p = atomicAdd(&g_cursor[r], 1);
        g_ecol[p] = c;
    }
}

// ---------------- score pass (warp per node): e + zinv ----------------
// Row layout of Qr/Kr: 256 floats = [head0 64][head1 64][head2 64][head3 64]
// lane l: float4 index l -> head l/16 (0 or 1); float4 index l+32 -> head 2 + l/16
__global__ __launch_bounds__(256) void gat_score(int n) {
    const int warp = (blockIdx.x * blockDim.x + threadIdx.x) >> 5;
    const int lane = threadIdx.x & 31;
    if (warp >= n) return;
    const int u = warp;
    const int p0 = g_rowptr[u], p1 = g_rowptr[u + 1];

    const float4* __restrict__ qp = (const float4*)(g_Qr + (size_t)u * 256);
    const float4 q0 = qp[lane];
    const float4 q1 = qp[lane + 32];

    float z0 = 0.f, z1 = 0.f;

    for (int p = p0; p < p1; p++) {
        const int v = g_ecol[p];
        const float4* __restrict__ kp = (const float4*)(g_Kr + (size_t)v * 256);
        const float4 k0 = kp[lane];
        const float4 k1 = kp[lane + 32];
        float s0 = q0.x * k0.x + q0.y * k0.y + q0.z * k0.z + q0.w * k0.w;
        float s1 = q1.x * k1.x + q1.y * k1.y + q1.z * k1.z + q1.w * k1.w;
        #pragma unroll
        for (int off = 8; off; off >>= 1) {
            s0 += __shfl_xor_sync(0xFFFFFFFFu, s0, off);
            s1 += __shfl_xor_sync(0xFFFFFFFFu, s1, off);
        }
        // lanes 0-15: (head0 in s0, head2 in s1); lanes 16-31: (head1, head3)
        float e0 = __expf(s0 * 0.125f);
        float e1 = __expf(s1 * 0.125f);
        z0 += e0;
        z1 += e1;
        float eh1 = __shfl_sync(0xFFFFFFFFu, e0, 16);
        float eh3 = __shfl_sync(0xFFFFFFFFu, e1, 16);
        if (lane == 0)
            *(float4*)(g_e + 4 * (size_t)p) = make_float4(e0, eh1, e1, eh3);
    }

    const float zh0 = __shfl_sync(0xFFFFFFFFu, z0, 0);
    const float zh1 = __shfl_sync(0xFFFFFFFFu, z0, 16);
    const float zh2 = __shfl_sync(0xFFFFFFFFu, z1, 0);
    const float zh3 = __shfl_sync(0xFFFFFFFFu, z1, 16);
    if (lane == 0) {
        *(float4*)(g_zinv + 4 * (size_t)u) = make_float4(
            1.0f / (zh0 + EPSV), 1.0f / (zh1 + EPSV),
            1.0f / (zh2 + EPSV), 1.0f / (zh3 + EPSV));
    }
}

// ---------------- aggregate pass (warp per node) ----------------
__global__ __launch_bounds__(256) void gat_aggr(float* __restrict__ out, int n) {
    const int warp = (blockIdx.x * blockDim.x + threadIdx.x) >> 5;
    const int lane = threadIdx.x & 31;
    if (warp >= n) return;
    const int u = warp;
    const int p0 = g_rowptr[u], p1 = g_rowptr[u + 1];

    const float4 zv = *(const float4*)(g_zinv + 4 * (size_t)u);
    const float i0 = zv.x, i1 = zv.y, i2 = zv.z, i3 = zv.w;

    float ax = 0.f, ay = 0.f;
    const int d2 = lane * 2;
    for (int p = p0; p < p1; p++) {
        const int v = g_ecol[p];
        const float4 ev = *(const float4*)(g_e + 4 * (size_t)p);
        const float a0 = ev.x * i0, a1 = ev.y * i1, a2 = ev.z * i2, a3 = ev.w * i3;
        const float* __restrict__ hb = g_Hb + (size_t)v * 256 + d2;
        const float2 h0 = *(const float2*)(hb);
        const float2 h1 = *(const float2*)(hb + 64);
        const float2 h2 = *(const float2*)(hb + 128);
        const float2 h3 = *(const float2*)(hb + 192);
        ax += a0 * h0.x + a1 * h1.x + a2 * h2.x + a3 * h3.x;
        ay += a0 * h0.y + a1 * h1.y + a2 * h2.y + a3 * h3.y;
    }
    *(float2*)(out + (size_t)u * 64 + d2) = make_float2(ax * 0.25f, ay * 0.25f);
}

// ---------------- launch ----------------
extern "C" void kernel_launch(void* const* d_in, const int* in_sizes, int n_in,
                              void* d_out, int out_size) {
    const float* x  = (const float*)d_in[0];
    const void*  ei = d_in[1];
    const float* Wq = (const float*)d_in[2];
    const float* Wk = (const float*)d_in[3];
    const float* Wh = (const float*)d_in[4];
    const float* bh = (const float*)d_in[5];
    float* out = (float*)d_out;

    const int n = in_sizes[0] / IN_DIM;
    const int E = in_sizes[1] / 2;

    gat_detect<<<1, 32>>>(ei, E);
    gat_wt<<<3, 256>>>(Wq, Wk, Wh);

    dim3 gg((n + BM - 1) / BM, 3);
    gat_gemm<<<gg, 256>>>(x, bh, n);

    gat_zero<<<(n + 255) / 256, 256>>>(n);
    gat_deg<<<(E + 255) / 256, 256>>>(ei, E);
    gat_scan<<<1, 1024>>>(n);
    gat_scatter<<<(E + 255) / 256, 256>>>(ei, E);

    const int nblocks = (n * 32 + 255) / 256;
    gat_score<<<nblocks, 256>>>(n);
    gat_aggr<<<nblocks, 256>>>(out, n);
}

// round 6
// speedup vs baseline: 1.8987x; 1.2226x over previous
#include <cuda_runtime.h>
#include <cuda_fp16.h>
#include <cstdint>

#define N_NODES 100000
#define N_EDGES 1600000
#define IN_DIM 128
#define OUT_DIM 64
#define NEG 0.2f
#define EPSV 1e-8f

// ---------------- scratch (device globals: allocation-free) ----------------
__device__ float  g_Qr[(size_t)N_NODES * 256];   // leaky(Q) fp32, [node][h*64+d]
__device__ __half g_Kh[(size_t)N_NODES * 256];   // leaky(K) fp16
__device__ float  g_Hb[(size_t)N_NODES * 256];   // H + bias fp32 (direct path: full precision)
__device__ float  g_Wt[(size_t)3 * 128 * 256];   // W transposed: [mtx][k][n]
__device__ float  g_e [(size_t)N_EDGES * 4];     // exp(score), [edge][head]
__device__ float  g_zinv[(size_t)N_NODES * 4];   // 1/(z+eps), [node][head]
__device__ int    g_ecol[N_EDGES];
__device__ int    g_deg [N_NODES];
__device__ int    g_rowptr[N_NODES + 1];
__device__ int    g_cursor[N_NODES];
__device__ int    g_bsum[128];
__device__ int    g_boff[128];
__device__ int    g_is64;

// ---------------- helpers ----------------
__device__ __forceinline__ uint32_t to_tf32(float x) {
    uint32_t r;
    asm("cvt.rna.tf32.f32 %0, %1;" : "=r"(r) : "f"(x));
    return r;
}
__device__ __forceinline__ void mma_tf32(float* d, const uint32_t* a, uint32_t b0, uint32_t b1) {
    asm volatile(
        "mma.sync.aligned.m16n8k8.row.col.f32.tf32.tf32.f32 "
        "{%0,%1,%2,%3}, {%4,%5,%6,%7}, {%8,%9}, {%0,%1,%2,%3};"
        : "+f"(d[0]), "+f"(d[1]), "+f"(d[2]), "+f"(d[3])
        : "r"(a[0]), "r"(a[1]), "r"(a[2]), "r"(a[3]), "r"(b0), "r"(b1));
}

// ---------------- dtype detection (int64 vs silently-int32 edge_index) -----
__global__ void gat_detect(const void* __restrict__ ei, int E) {
    if (threadIdx.x == 0 && blockIdx.x == 0) {
        const long long* p = (const long long*)ei;
        const int stride = E / 16;
        int ok = 1;
        #pragma unroll
        for (int i = 0; i < 16; i++) {
            long long v = p[(size_t)i * stride];
            if (v < 0 || v >= (long long)N_NODES) ok = 0;
        }
        g_is64 = ok;
    }
}

__device__ __forceinline__ int load_idx(const void* __restrict__ ei, int pos) {
    if (g_is64) return (int)((const long long*)ei)[pos];
    return ((const int*)ei)[pos];
}

// ---------------- W transpose: [n][k] -> [k][n] ----------------
__global__ void gat_wt(const float* __restrict__ Wq, const float* __restrict__ Wk,
                       const float* __restrict__ Wh) {
    const float* __restrict__ W = (blockIdx.x == 0) ? Wq : ((blockIdx.x == 1) ? Wk : Wh);
    float* __restrict__ dst = g_Wt + (size_t)blockIdx.x * 128 * 256;
    for (int i = threadIdx.x; i < 256 * 128; i += blockDim.x) {
        const int nrow = i >> 7;
        const int k    = i & 127;
        dst[k * 256 + nrow] = W[i];
    }
}

// ---------------- mma.sync tf32 projection GEMM ----------------
// CTA tile: 64 rows x 256 cols, K=128 chunked by 32.
#define BM 64
#define BK 32
#define LDA 36      // As[m][k]: bank = (4*row + k) % 32  -> conflict-free frags
#define LDB 264     // Bs[k][n]: bank = (8*k + n) % 32    -> conflict-free frags

__global__ __launch_bounds__(256) void gat_gemm(
    const float* __restrict__ x, const float* __restrict__ bh, int n)
{
    __shared__ float As[BM * LDA];
    __shared__ float Bs[BK * LDB];

    const int tid  = threadIdx.x;
    const int wid  = tid >> 5;
    const int lane = tid & 31;
    const int m0   = blockIdx.x * BM;
    const int mtx  = blockIdx.y;                 // 0=Q, 1=K, 2=H
    const float* __restrict__ Wt = g_Wt + (size_t)mtx * 128 * 256;

    const int wr = (wid >> 2) * 32;
    const int wc = (wid & 3) * 64;
    const int lr = lane >> 2;
    const int lc = lane & 3;

    float acc[2][8][4];
    #pragma unroll
    for (int i = 0; i < 2; i++)
        #pragma unroll
        for (int j = 0; j < 8; j++)
            #pragma unroll
            for (int t = 0; t < 4; t++) acc[i][j][t] = 0.f;

    for (int kc = 0; kc < IN_DIM; kc += BK) {
        #pragma unroll
        for (int i = tid; i < 512; i += 256) {
            const int row = i >> 3;
            const int kq  = (i & 7) * 4;
            const int grow = m0 + row;
            float4 v = make_float4(0.f, 0.f, 0.f, 0.f);
            if (grow < n) v = *(const float4*)(x + (size_t)grow * IN_DIM + kc + kq);
            uint4 t;
            t.x = to_tf32(v.x); t.y = to_tf32(v.y); t.z = to_tf32(v.z); t.w = to_tf32(v.w);
            *(uint4*)&As[row * LDA + kq] = t;
        }
        #pragma unroll
        for (int i = tid; i < 2048; i += 256) {
            const int k  = i >> 6;
            const int nq = (i & 63) * 4;
            float4 v = *(const float4*)(Wt + (size_t)(kc + k) * 256 + nq);
            uint4 t;
            t.x = to_tf32(v.x); t.y = to_tf32(v.y); t.z = to_tf32(v.z); t.w = to_tf32(v.w);
            *(uint4*)&Bs[k * LDB + nq] = t;
        }
        __syncthreads();

        #pragma unroll
        for (int ks = 0; ks < 4; ks++) {
            uint32_t a[2][4];
            #pragma unroll
            for (int i = 0; i < 2; i++) {
                const float* ap = &As[(wr + i * 16 + lr) * LDA + ks * 8 + lc];
                a[i][0] = __float_as_uint(ap[0]);
                a[i][1] = __float_as_uint(ap[8 * LDA]);
                a[i][2] = __float_as_uint(ap[4]);
                a[i][3] = __float_as_uint(ap[8 * LDA + 4]);
            }
            #pragma unroll
            for (int j = 0; j < 8; j++) {
                const float* bp = &Bs[(ks * 8 + lc) * LDB + wc + j * 8 + lr];
                const uint32_t b0 = __float_as_uint(bp[0]);
                const uint32_t b1 = __float_as_uint(bp[4 * LDB]);
                mma_tf32(acc[0][j], a[0], b0, b1);
                mma_tf32(acc[1][j], a[1], b0, b1);
            }
        }
        __syncthreads();
    }

    // epilogue: Q -> fp32 + leaky; K -> fp16 + leaky; H -> fp32 + bias
    #pragma unroll
    for (int i = 0; i < 2; i++) {
        const int r0 = m0 + wr + i * 16 + lr;
        const int r1 = r0 + 8;
        #pragma unroll
        for (int j = 0; j < 8; j++) {
            const int col = wc + j * 8 + lc * 2;
            float2 v0 = make_float2(acc[i][j][0], acc[i][j][1]);
            float2 v1 = make_float2(acc[i][j][2], acc[i][j][3]);
            if (mtx < 2) {
                v0.x = v0.x > 0.f ? v0.x : NEG * v0.x;
                v0.y = v0.y > 0.f ? v0.y : NEG * v0.y;
                v1.x = v1.x > 0.f ? v1.x : NEG * v1.x;
                v1.y = v1.y > 0.f ? v1.y : NEG * v1.y;
            } else {
                const float bx = bh[col], by = bh[col + 1];
                v0.x += bx; v0.y += by;
                v1.x += bx; v1.y += by;
            }
            if (mtx == 0) {
                if (r0 < n) *(float2*)(g_Qr + (size_t)r0 * 256 + col) = v0;
                if (r1 < n) *(float2*)(g_Qr + (size_t)r1 * 256 + col) = v1;
            } else if (mtx == 1) {
                if (r0 < n) *(__half2*)(g_Kh + (size_t)r0 * 256 + col) = __floats2half2_rn(v0.x, v0.y);
                if (r1 < n) *(__half2*)(g_Kh + (size_t)r1 * 256 + col) = __floats2half2_rn(v1.x, v1.y);
            } else {
                if (r0 < n) *(float2*)(g_Hb + (size_t)r0 * 256 + col) = v0;
                if (r1 < n) *(float2*)(g_Hb + (size_t)r1 * 256 + col) = v1;
            }
        }
    }
}

// ---------------- CSR build ----------------
__global__ void gat_zero(int n) {
    int i = blockIdx.x * blockDim.x + threadIdx.x;
    if (i < n) g_deg[i] = 0;
}

__global__ void gat_deg(const void* __restrict__ ei, int E) {
    int e = blockIdx.x * blockDim.x + threadIdx.x;
    if (e < E) atomicAdd(&g_deg[load_idx(ei, e)], 1);
}

// block-local exclusive scan (1024 thr); writes local prefix + block total
__global__ void gat_scan1(int n) {
    __shared__ int warpsum[32];
    const int tid  = threadIdx.x;
    const int lane = tid & 31;
    const int wid  = tid >> 5;
    const int i = blockIdx.x * 1024 + tid;
    const int v = (i < n) ? g_deg[i] : 0;
    int s = v;
    #pragma unroll
    for (int off = 1; off < 32; off <<= 1) {
        int t = __shfl_up_sync(0xFFFFFFFFu, s, off);
        if (lane >= off) s += t;
    }
    if (lane == 31) warpsum[wid] = s;
    __syncthreads();
    if (wid == 0) {
        int w = warpsum[lane];
        #pragma unroll
        for (int off = 1; off < 32; off <<= 1) {
            int t = __shfl_up_sync(0xFFFFFFFFu, w, off);
            if (lane >= off) w += t;
        }
        warpsum[lane] = w;
    }
    __syncthreads();
    const int wbase = (wid == 0) ? 0 : warpsum[wid - 1];
    if (i < n) g_rowptr[i] = wbase + s - v;       // block-local exclusive
    if (tid == 1023) g_bsum[blockIdx.x] = warpsum[31];
}

// scan the block sums (nb <= 128), write exclusive offsets + grand total
__global__ void gat_scan2(int nb, int n) {
    const int tid  = threadIdx.x;   // 128 threads
    const int lane = tid & 31;
    const int wid  = tid >> 5;
    __shared__ int warpsum[4];
    const int v = (tid < nb) ? g_bsum[tid] : 0;
    int s = v;
    #pragma unroll
    for (int off = 1; off < 32; off <<= 1) {
        int t = __shfl_up_sync(0xFFFFFFFFu, s, off);
        if (lane >= off) s += t;
    }
    if (lane == 31) warpsum[wid] = s;
    __syncthreads();
    int wbase = 0;
    #pragma unroll
    for (int w = 0; w < 4; w++) if (w < wid) wbase += warpsum[w];
    if (tid < nb) g_boff[tid] = wbase + s - v;
    if (tid == 127) g_rowptr[n] = wbase + s;
}

// apply block offsets, init cursor
__global__ void gat_scan3(int n) {
    const int i = blockIdx.x * blockDim.x + threadIdx.x;
    if (i < n) {
        const int r = g_rowptr[i] + g_boff[blockIdx.x >> 2];   // 256 thr * 4 blocks = 1024
        g_rowptr[i] = r;
        g_cursor[i] = r;
    }
}

__global__ void gat_scatter(const void* __restrict__ ei, int E) {
    int e = blockIdx.x * blockDim.x + threadIdx.x;
    if (e < E) {
        int r = load_idx(ei, e);
        int c = load_idx(ei, E + e);
        int p = atomicAdd(&g_cursor[r], 1);
        g_ecol[p] = c;
    }
}

// ---------------- score pass (warp per node): e + zinv ----------------
// K row = 512 bytes fp16. lane l loads uint4 (8 halves) at byte offset l*16.
// head h = l>>3, slot t = l&7 covers dims t*8..t*8+7.
__global__ __launch_bounds__(256) void gat_score(int n) {
    const int warp = (blockIdx.x * blockDim.x + threadIdx.x) >> 5;
    const int lane = threadIdx.x & 31;
    if (warp >= n) return;
    const int u = warp;
    const int h = lane >> 3;
    const int t = lane & 7;
    const int p0 = g_rowptr[u], p1 = g_rowptr[u + 1];

    // q: 8 fp32 for this lane's (head, dim-slot)
    float qv[8];
    {
        const float4* qp = (const float4*)(g_Qr + (size_t)u * 256 + h * 64 + t * 8);
        float4 a = qp[0], b = qp[1];
        qv[0] = a.x; qv[1] = a.y; qv[2] = a.z; qv[3] = a.w;
        qv[4] = b.x; qv[5] = b.y; qv[6] = b.z; qv[7] = b.w;
    }

    float z = 0.f;
    for (int p = p0; p < p1; p++) {
        const int v = g_ecol[p];
        const uint4 kv = *(const uint4*)((const char*)g_Kh + (size_t)v * 512 + lane * 16);
        const float2 k0 = __half22float2(*(const __half2*)&kv.x);
        const float2 k1 = __half22float2(*(const __half2*)&kv.y);
        const float2 k2 = __half22float2(*(const __half2*)&kv.z);
        const float2 k3 = __half22float2(*(const __half2*)&kv.w);
        float s = qv[0] * k0.x + qv[1] * k0.y + qv[2] * k1.x + qv[3] * k1.y
                + qv[4] * k2.x + qv[5] * k2.y + qv[6] * k3.x + qv[7] * k3.y;
        s += __shfl_xor_sync(0xFFFFFFFFu, s, 4);
        s += __shfl_xor_sync(0xFFFFFFFFu, s, 2);
        s += __shfl_xor_sync(0xFFFFFFFFu, s, 1);
        const float e = __expf(s * 0.125f);
        z += e;
        if (t == 0) g_e[4 * (size_t)p + h] = e;
    }
    if (t == 0) g_zinv[4 * (size_t)u + h] = 1.0f / (z + EPSV);
}

// ---------------- aggregate pass (warp per node), fp32 H ----------------
// lane l handles out dims 2l, 2l+1: head h at float2 index h*32 + l of the row.
__global__ __launch_bounds__(256) void gat_aggr(float* __restrict__ out, int n) {
    const int warp = (blockIdx.x * blockDim.x + threadIdx.x) >> 5;
    const int lane = threadIdx.x & 31;
    if (warp >= n) return;
    const int u = warp;
    const int p0 = g_rowptr[u], p1 = g_rowptr[u + 1];

    const float4 zv = *(const float4*)(g_zinv + 4 * (size_t)u);
    const float i0 = zv.x, i1 = zv.y, i2 = zv.z, i3 = zv.w;

    float ax = 0.f, ay = 0.f;
    for (int p = p0; p < p1; p++) {
        const int v = g_ecol[p];
        const float4 ev = *(const float4*)(g_e + 4 * (size_t)p);
        const float a0 = ev.x * i0, a1 = ev.y * i1, a2 = ev.z * i2, a3 = ev.w * i3;
        const float2* __restrict__ hb = (const float2*)g_Hb + (size_t)v * 128 + lane;
        const float2 h0 = hb[0];
        const float2 h1 = hb[32];
        const float2 h2 = hb[64];
        const float2 h3 = hb[96];
        ax += a0 * h0.x + a1 * h1.x + a2 * h2.x + a3 * h3.x;
        ay += a0 * h0.y + a1 * h1.y + a2 * h2.y + a3 * h3.y;
    }
    *(float2*)(out + (size_t)u * 64 + lane * 2) = make_float2(ax * 0.25f, ay * 0.25f);
}

// ---------------- launch ----------------
extern "C" void kernel_launch(void* const* d_in, const int* in_sizes, int n_in,
                              void* d_out, int out_size) {
    const float* x  = (const float*)d_in[0];
    const void*  ei = d_in[1];
    const float* Wq = (const float*)d_in[2];
    const float* Wk = (const float*)d_in[3];
    const float* Wh = (const float*)d_in[4];
    const float* bh = (const float*)d_in[5];
    float* out = (float*)d_out;

    const int n = in_sizes[0] / IN_DIM;
    const int E = in_sizes[1] / 2;
    const int nb = (n + 1023) / 1024;

    gat_detect<<<1, 32>>>(ei, E);
    gat_wt<<<3, 256>>>(Wq, Wk, Wh);

    dim3 gg((n + BM - 1) / BM, 3);
    gat_gemm<<<gg, 256>>>(x, bh, n);

    gat_zero<<<(n + 255) / 256, 256>>>(n);
    gat_deg<<<(E + 255) / 256, 256>>>(ei, E);
    gat_scan1<<<nb, 1024>>>(n);
    gat_scan2<<<1, 128>>>(nb, n);
    gat_scan3<<<nb * 4, 256>>>(n);
    gat_scatter<<<(E + 255) / 256, 256>>>(ei, E);

    const int nblocks = (n * 32 + 255) / 256;
    gat_score<<<nblocks, 256>>>(n);
    gat_aggr<<<nblocks, 256>>>(out, n);
}

// round 8
// speedup vs baseline: 1.9957x; 1.0511x over previous
#include <cuda_runtime.h>
#include <cuda_fp16.h>
#include <cstdint>

#define N_NODES 100000
#define N_EDGES 1600000
#define IN_DIM 128
#define OUT_DIM 64
#define NEG 0.2f
#define EPSV 1e-8f

// ---------------- scratch (device globals: allocation-free) ----------------
__device__ float  g_Qr[(size_t)N_NODES * 256];   // leaky(Q) fp32, [node][h*64+d]
__device__ __half g_Kh[(size_t)N_NODES * 256];   // leaky(K) fp16
__device__ __half g_Hh[(size_t)N_NODES * 256];   // H + bias, fp16
__device__ float  g_Wt[(size_t)3 * 128 * 256];   // W transposed: [mtx][k][n]
__device__ float  g_e [(size_t)N_EDGES * 4];     // exp(score), [edge][head]
__device__ float  g_zinv[(size_t)N_NODES * 4];   // 1/(z+eps), [node][head]
__device__ int    g_ecol[N_EDGES];
__device__ int    g_deg [N_NODES];
__device__ int    g_rowptr[N_NODES + 1];
__device__ int    g_cursor[N_NODES];
__device__ int    g_bsum[128];
__device__ int    g_boff[128];
__device__ int    g_is64;

// ---------------- helpers ----------------
__device__ __forceinline__ uint32_t to_tf32(float x) {
    uint32_t r;
    asm("cvt.rna.tf32.f32 %0, %1;" : "=r"(r) : "f"(x));
    return r;
}
__device__ __forceinline__ void mma_tf32(float* d, const uint32_t* a, uint32_t b0, uint32_t b1) {
    asm volatile(
        "mma.sync.aligned.m16n8k8.row.col.f32.tf32.tf32.f32 "
        "{%0,%1,%2,%3}, {%4,%5,%6,%7}, {%8,%9}, {%0,%1,%2,%3};"
        : "+f"(d[0]), "+f"(d[1]), "+f"(d[2]), "+f"(d[3])
        : "r"(a[0]), "r"(a[1]), "r"(a[2]), "r"(a[3]), "r"(b0), "r"(b1));
}

// ---------------- dtype detection (int64 vs silently-int32 edge_index) -----
__global__ void gat_detect(const void* __restrict__ ei, int E) {
    if (threadIdx.x == 0 && blockIdx.x == 0) {
        const long long* p = (const long long*)ei;
        const int stride = E / 16;
        int ok = 1;
        #pragma unroll
        for (int i = 0; i < 16; i++) {
            long long v = p[(size_t)i * stride];
            if (v < 0 || v >= (long long)N_NODES) ok = 0;
        }
        g_is64 = ok;
    }
}

__device__ __forceinline__ int load_idx(const void* __restrict__ ei, int pos) {
    if (g_is64) return (int)((const long long*)ei)[pos];
    return ((const int*)ei)[pos];
}

// ---------------- W transpose: [n][k] -> [k][n] ----------------
__global__ void gat_wt(const float* __restrict__ Wq, const float* __restrict__ Wk,
                       const float* __restrict__ Wh) {
    const float* __restrict__ W = (blockIdx.x == 0) ? Wq : ((blockIdx.x == 1) ? Wk : Wh);
    float* __restrict__ dst = g_Wt + (size_t)blockIdx.x * 128 * 256;
    for (int i = threadIdx.x; i < 256 * 128; i += blockDim.x) {
        const int nrow = i >> 7;
        const int k    = i & 127;
        dst[k * 256 + nrow] = W[i];
    }
}

// ---------------- mma.sync tf32 GEMM + fused degree count ----------------
// gridDim = (1563, 4): y<3 -> GEMM matrix y (0=Q,1=K,2=H); y==3 -> deg count
// (deg atomics = LTS work hides under the tensor/smem-bound GEMM blocks).
#define BM 64
#define BK 32
#define LDA 36      // As[m][k]: bank = (4*row + k) % 32  -> conflict-free frags
#define LDB 264     // Bs[k][n]: bank = (8*k + n) % 32    -> conflict-free frags

__global__ __launch_bounds__(256) void gat_gemm(
    const float* __restrict__ x, const float* __restrict__ bh,
    const void* __restrict__ ei, int E, int n)
{
    if (blockIdx.y == 3) {
        const int stride = gridDim.x * 256;
        for (int e = blockIdx.x * 256 + threadIdx.x; e < E; e += stride)
            atomicAdd(&g_deg[load_idx(ei, e)], 1);
        return;
    }

    __shared__ float As[BM * LDA];
    __shared__ float Bs[BK * LDB];

    const int tid  = threadIdx.x;
    const int wid  = tid >> 5;
    const int lane = tid & 31;
    const int m0   = blockIdx.x * BM;
    const int mtx  = blockIdx.y;                 // 0=Q, 1=K, 2=H
    const float* __restrict__ Wt = g_Wt + (size_t)mtx * 128 * 256;

    const int wr = (wid >> 2) * 32;
    const int wc = (wid & 3) * 64;
    const int lr = lane >> 2;
    const int lc = lane & 3;

    float acc[2][8][4];
    #pragma unroll
    for (int i = 0; i < 2; i++)
        #pragma unroll
        for (int j = 0; j < 8; j++)
            #pragma unroll
            for (int t = 0; t < 4; t++) acc[i][j][t] = 0.f;

    for (int kc = 0; kc < IN_DIM; kc += BK) {
        #pragma unroll
        for (int i = tid; i < 512; i += 256) {
            const int row = i >> 3;
            const int kq  = (i & 7) * 4;
            const int grow = m0 + row;
            float4 v = make_float4(0.f, 0.f, 0.f, 0.f);
            if (grow < n) v = *(const float4*)(x + (size_t)grow * IN_DIM + kc + kq);
            uint4 t;
            t.x = to_tf32(v.x); t.y = to_tf32(v.y); t.z = to_tf32(v.z); t.w = to_tf32(v.w);
            *(uint4*)&As[row * LDA + kq] = t;
        }
        #pragma unroll
        for (int i = tid; i < 2048; i += 256) {
            const int k  = i >> 6;
            const int nq = (i & 63) * 4;
            float4 v = *(const float4*)(Wt + (size_t)(kc + k) * 256 + nq);
            uint4 t;
            t.x = to_tf32(v.x); t.y = to_tf32(v.y); t.z = to_tf32(v.z); t.w = to_tf32(v.w);
            *(uint4*)&Bs[k * LDB + nq] = t;
        }
        __syncthreads();

        #pragma unroll
        for (int ks = 0; ks < 4; ks++) {
            uint32_t a[2][4];
            #pragma unroll
            for (int i = 0; i < 2; i++) {
                const float* ap = &As[(wr + i * 16 + lr) * LDA + ks * 8 + lc];
                a[i][0] = __float_as_uint(ap[0]);
                a[i][1] = __float_as_uint(ap[8 * LDA]);
                a[i][2] = __float_as_uint(ap[4]);
                a[i][3] = __float_as_uint(ap[8 * LDA + 4]);
            }
            #pragma unroll
            for (int j = 0; j < 8; j++) {
                const float* bp = &Bs[(ks * 8 + lc) * LDB + wc + j * 8 + lr];
                const uint32_t b0 = __float_as_uint(bp[0]);
                const uint32_t b1 = __float_as_uint(bp[4 * LDB]);
                mma_tf32(acc[0][j], a[0], b0, b1);
                mma_tf32(acc[1][j], a[1], b0, b1);
            }
        }
        __syncthreads();
    }

    // epilogue: Q -> fp32 + leaky; K -> fp16 + leaky; H -> fp16 + bias
    #pragma unroll
    for (int i = 0; i < 2; i++) {
        const int r0 = m0 + wr + i * 16 + lr;
        const int r1 = r0 + 8;
        #pragma unroll
        for (int j = 0; j < 8; j++) {
            const int col = wc + j * 8 + lc * 2;
            float2 v0 = make_float2(acc[i][j][0], acc[i][j][1]);
            float2 v1 = make_float2(acc[i][j][2], acc[i][j][3]);
            if (mtx < 2) {
                v0.x = v0.x > 0.f ? v0.x : NEG * v0.x;
                v0.y = v0.y > 0.f ? v0.y : NEG * v0.y;
                v1.x = v1.x > 0.f ? v1.x : NEG * v1.x;
                v1.y = v1.y > 0.f ? v1.y : NEG * v1.y;
            } else {
                const float bx = bh[col], by = bh[col + 1];
                v0.x += bx; v0.y += by;
                v1.x += bx; v1.y += by;
            }
            if (mtx == 0) {
                if (r0 < n) *(float2*)(g_Qr + (size_t)r0 * 256 + col) = v0;
                if (r1 < n) *(float2*)(g_Qr + (size_t)r1 * 256 + col) = v1;
            } else {
                __half* __restrict__ dsth = (mtx == 1) ? g_Kh : g_Hh;
                if (r0 < n) *(__half2*)(dsth + (size_t)r0 * 256 + col) = __floats2half2_rn(v0.x, v0.y);
                if (r1 < n) *(__half2*)(dsth + (size_t)r1 * 256 + col) = __floats2half2_rn(v1.x, v1.y);
            }
        }
    }
}

// ---------------- CSR build ----------------
__global__ void gat_zero(int n) {
    int i = blockIdx.x * blockDim.x + threadIdx.x;
    if (i < n) g_deg[i] = 0;
}

// block-local exclusive scan (1024 thr); writes local prefix + block total
__global__ void gat_scan1(int n) {
    __shared__ int warpsum[32];
    const int tid  = threadIdx.x;
    const int lane = tid & 31;
    const int wid  = tid >> 5;
    const int i = blockIdx.x * 1024 + tid;
    const int v = (i < n) ? g_deg[i] : 0;
    int s = v;
    #pragma unroll
    for (int off = 1; off < 32; off <<= 1) {
        int t = __shfl_up_sync(0xFFFFFFFFu, s, off);
        if (lane >= off) s += t;
    }
    if (lane == 31) warpsum[wid] = s;
    __syncthreads();
    if (wid == 0) {
        int w = warpsum[lane];
        #pragma unroll
        for (int off = 1; off < 32; off <<= 1) {
            int t = __shfl_up_sync(0xFFFFFFFFu, w, off);
            if (lane >= off) w += t;
        }
        warpsum[lane] = w;
    }
    __syncthreads();
    const int wbase = (wid == 0) ? 0 : warpsum[wid - 1];
    if (i < n) g_rowptr[i] = wbase + s - v;       // block-local exclusive
    if (tid == 1023) g_bsum[blockIdx.x] = warpsum[31];
}

// scan the block sums (nb <= 128), write exclusive offsets + grand total
__global__ void gat_scan2(int nb, int n) {
    const int tid  = threadIdx.x;   // 128 threads
    const int lane = tid & 31;
    const int wid  = tid >> 5;
    __shared__ int warpsum[4];
    const int v = (tid < nb) ? g_bsum[tid] : 0;
    int s = v;
    #pragma unroll
    for (int off = 1; off < 32; off <<= 1) {
        int t = __shfl_up_sync(0xFFFFFFFFu, s, off);
        if (lane >= off) s += t;
    }
    if (lane == 31) warpsum[wid] = s;
    __syncthreads();
    int wbase = 0;
    #pragma unroll
    for (int w = 0; w < 4; w++) if (w < wid) wbase += warpsum[w];
    if (tid < nb) g_boff[tid] = wbase + s - v;
    if (tid == 127) g_rowptr[n] = wbase + s;
}

// apply block offsets, init cursor
__global__ void gat_scan3(int n) {
    const int i = blockIdx.x * blockDim.x + threadIdx.x;
    if (i < n) {
        const int r = g_rowptr[i] + g_boff[blockIdx.x >> 2];   // 256 thr * 4 blocks = 1024
        g_rowptr[i] = r;
        g_cursor[i] = r;
    }
}

__global__ void gat_scatter(const void* __restrict__ ei, int E) {
    int e = blockIdx.x * blockDim.x + threadIdx.x;
    if (e < E) {
        int r = load_idx(ei, e);
        int c = load_idx(ei, E + e);
        int p = atomicAdd(&g_cursor[r], 1);
        g_ecol[p] = c;
    }
}

// ---------------- score pass (warp per node): e + zinv ----------------
// K row = 512 bytes fp16. lane l loads uint4 (8 halves) at byte offset l*16.
// head h = l>>3, slot t = l&7 covers dims t*8..t*8+7.
__global__ __launch_bounds__(256) void gat_score(int n) {
    const int warp = (blockIdx.x * blockDim.x + threadIdx.x) >> 5;
    const int lane = threadIdx.x & 31;
    if (warp >= n) return;
    const int u = warp;
    const int h = lane >> 3;
    const int t = lane & 7;
    const int p0 = g_rowptr[u], p1 = g_rowptr[u + 1];

    float qv[8];
    {
        const float4* qp = (const float4*)(g_Qr + (size_t)u * 256 + h * 64 + t * 8);
        float4 a = qp[0], b = qp[1];
        qv[0] = a.x; qv[1] = a.y; qv[2] = a.z; qv[3] = a.w;
        qv[4] = b.x; qv[5] = b.y; qv[6] = b.z; qv[7] = b.w;
    }

    float z = 0.f;
    for (int p = p0; p < p1; p++) {
        const int v = g_ecol[p];
        const uint4 kv = *(const uint4*)((const char*)g_Kh + (size_t)v * 512 + lane * 16);
        const float2 k0 = __half22float2(*(const __half2*)&kv.x);
        const float2 k1 = __half22float2(*(const __half2*)&kv.y);
        const float2 k2 = __half22float2(*(const __half2*)&kv.z);
        const float2 k3 = __half22float2(*(const __half2*)&kv.w);
        float s = qv[0] * k0.x + qv[1] * k0.y + qv[2] * k1.x + qv[3] * k1.y
                + qv[4] * k2.x + qv[5] * k2.y + qv[6] * k3.x + qv[7] * k3.y;
        s += __shfl_xor_sync(0xFFFFFFFFu, s, 4);
        s += __shfl_xor_sync(0xFFFFFFFFu, s, 2);
        s += __shfl_xor_sync(0xFFFFFFFFu, s, 1);
        const float e = __expf(s * 0.125f);
        z += e;
        if (t == 0) g_e[4 * (size_t)p + h] = e;
    }
    if (t == 0) g_zinv[4 * (size_t)u + h] = 1.0f / (z + EPSV);
}

// ---------------- aggregate pass (warp per node), fp16 H ----------------
// lane l handles out dims 2l, 2l+1: head h at half2 index h*32 + l of the row.
__global__ __launch_bounds__(256) void gat_aggr(float* __restrict__ out, int n) {
    const int warp = (blockIdx.x * blockDim.x + threadIdx.x) >> 5;
    const int lane = threadIdx.x & 31;
    if (warp >= n) return;
    const int u = warp;
    const int p0 = g_rowptr[u], p1 = g_rowptr[u + 1];

    const float4 zv = *(const float4*)(g_zinv + 4 * (size_t)u);
    const float i0 = zv.x, i1 = zv.y, i2 = zv.z, i3 = zv.w;

    float ax = 0.f, ay = 0.f;
    for (int p = p0; p < p1; p++) {
        const int v = g_ecol[p];
        const float4 ev = *(const float4*)(g_e + 4 * (size_t)p);
        const float a0 = ev.x * i0, a1 = ev.y * i1, a2 = ev.z * i2, a3 = ev.w * i3;
        const __half2* __restrict__ hb = (const __half2*)g_Hh + (size_t)v * 128 + lane;
        const float2 h0 = __half22float2(hb[0]);
        const float2 h1 = __half22float2(hb[32]);
        const float2 h2 = __half22float2(hb[64]);
        const float2 h3 = __half22float2(hb[96]);
        ax += a0 * h0.x + a1 * h1.x + a2 * h2.x + a3 * h3.x;
        ay += a0 * h0.y + a1 * h1.y + a2 * h2.y + a3 * h3.y;
    }
    *(float2*)(out + (size_t)u * 64 + lane * 2) = make_float2(ax * 0.25f, ay * 0.25f);
}

// ---------------- launch ----------------
extern "C" void kernel_launch(void* const* d_in, const int* in_sizes, int n_in,
                              void* d_out, int out_size) {
    const float* x  = (const float*)d_in[0];
    const void*  ei = d_in[1];
    const float* Wq = (const float*)d_in[2];
    const float* Wk = (const float*)d_in[3];
    const float* Wh = (const float*)d_in[4];
    const float* bh = (const float*)d_in[5];
    float* out = (float*)d_out;

    const int n = in_sizes[0] / IN_DIM;
    const int E = in_sizes[1] / 2;
    const int nb = (n + 1023) / 1024;

    gat_detect<<<1, 32>>>(ei, E);
    gat_wt<<<3, 256>>>(Wq, Wk, Wh);
    gat_zero<<<(n + 255) / 256, 256>>>(n);

    dim3 gg((n + BM - 1) / BM, 4);      // y<3: GEMM Q/K/H; y==3: deg count
    gat_gemm<<<gg, 256>>>(x, bh, ei, E, n);

    gat_scan1<<<nb, 1024>>>(n);
    gat_scan2<<<1, 128>>>(nb, n);
    gat_scan3<<<nb * 4, 256>>>(n);
    gat_scatter<<<(E + 255) / 256, 256>>>(ei, E);

    const int nblocks = (n * 32 + 255) / 256;
    gat_score<<<nblocks, 256>>>(n);
    gat_aggr<<<nblocks, 256>>>(out, n);
}

// round 9
// speedup vs baseline: 2.3909x; 1.1980x over previous
#include <cuda_runtime.h>
#include <cuda_fp16.h>
#include <cstdint>

#define N_NODES 100000
#define N_EDGES 1600000
#define IN_DIM 128
#define OUT_DIM 64
#define NEG 0.2f
#define EPSV 1e-8f

// ---------------- scratch (device globals: allocation-free) ----------------
__device__ float  g_Qr[(size_t)N_NODES * 256];   // leaky(Q) fp32, [node][h*64+d]
__device__ __half g_Kh[(size_t)N_NODES * 256];   // leaky(K) fp16
__device__ __half g_Hh[(size_t)N_NODES * 256];   // H + bias, fp16
__device__ __half g_xh[(size_t)N_NODES * 128];   // x in fp16
__device__ __half g_Wh[(size_t)3 * 256 * 128];   // W in fp16, [mtx][n][k] (orig layout)
__device__ float  g_e [(size_t)N_EDGES * 4];     // exp(score), [edge][head]
__device__ float  g_zinv[(size_t)N_NODES * 4];   // 1/(z+eps), [node][head]
__device__ int    g_ecol[N_EDGES];
__device__ int    g_deg [N_NODES];
__device__ int    g_rowptr[N_NODES + 1];
__device__ int    g_cursor[N_NODES];
__device__ int    g_bsum[128];
__device__ int    g_boff[128];
__device__ int    g_is64;

// ---------------- helpers ----------------
__device__ __forceinline__ void mma_f16(float* d, const uint32_t* a, uint32_t b0, uint32_t b1) {
    asm volatile(
        "mma.sync.aligned.m16n8k16.row.col.f32.f16.f16.f32 "
        "{%0,%1,%2,%3}, {%4,%5,%6,%7}, {%8,%9}, {%0,%1,%2,%3};"
        : "+f"(d[0]), "+f"(d[1]), "+f"(d[2]), "+f"(d[3])
        : "r"(a[0]), "r"(a[1]), "r"(a[2]), "r"(a[3]), "r"(b0), "r"(b1));
}
__device__ __forceinline__ void ldm4(uint32_t* r, uint32_t addr) {
    asm volatile("ldmatrix.sync.aligned.m8n8.x4.shared.b16 {%0,%1,%2,%3}, [%4];"
                 : "=r"(r[0]), "=r"(r[1]), "=r"(r[2]), "=r"(r[3]) : "r"(addr));
}

// ---------------- dtype detection (int64 vs silently-int32 edge_index) -----
__global__ void gat_detect(const void* __restrict__ ei, int E) {
    if (threadIdx.x == 0 && blockIdx.x == 0) {
        const long long* p = (const long long*)ei;
        const int stride = E / 16;
        int ok = 1;
        #pragma unroll
        for (int i = 0; i < 16; i++) {
            long long v = p[(size_t)i * stride];
            if (v < 0 || v >= (long long)N_NODES) ok = 0;
        }
        g_is64 = ok;
    }
}

__device__ __forceinline__ int load_idx(const void* __restrict__ ei, int pos) {
    if (g_is64) return (int)((const long long*)ei)[pos];
    return ((const int*)ei)[pos];
}

// ---------------- fp16 conversions ----------------
__global__ void gat_xh(const float* __restrict__ x, int total2) {
    const int i = blockIdx.x * blockDim.x + threadIdx.x;   // handles 2 floats
    if (i < total2) {
        const float2 v = *(const float2*)(x + (size_t)i * 2);
        *(__half2*)(g_xh + (size_t)i * 2) = __floats2half2_rn(v.x, v.y);
    }
}
__global__ void gat_wh(const float* __restrict__ Wq, const float* __restrict__ Wk,
                       const float* __restrict__ Wh) {
    const float* __restrict__ W = (blockIdx.x == 0) ? Wq : ((blockIdx.x == 1) ? Wk : Wh);
    __half* __restrict__ dst = g_Wh + (size_t)blockIdx.x * 256 * 128;
    for (int i = threadIdx.x; i < 256 * 128 / 2; i += blockDim.x) {
        const float2 v = *(const float2*)(W + (size_t)i * 2);
        *(__half2*)(dst + (size_t)i * 2) = __floats2half2_rn(v.x, v.y);
    }
}

// ---------------- fp16 mma GEMM + fused degree count ----------------
// gridDim = (ceil(n/64), 4): y<3 -> GEMM matrix y (0=Q,1=K,2=H); y==3 -> deg.
// CTA tile 64 x 256, K chunked by 64; warp tile 32x64 = 2 m-atoms x 8 n-atoms
// of m16n8k16. A/B smem row stride 72 halves (144 B) -> ldmatrix conflict-free.
#define BM 64
#define BKH 64
#define LDH 72

__global__ __launch_bounds__(256, 2) void gat_gemm(
    const float* __restrict__ bh, const void* __restrict__ ei, int E, int n)
{
    if (blockIdx.y == 3) {
        const int stride = gridDim.x * 256;
        for (int e = blockIdx.x * 256 + threadIdx.x; e < E; e += stride)
            atomicAdd(&g_deg[load_idx(ei, e)], 1);
        return;
    }

    __shared__ __half As[BM * LDH];     //  9216 B
    __shared__ __half Bs[256 * LDH];    // 36864 B

    const int tid  = threadIdx.x;
    const int wid  = tid >> 5;
    const int lane = tid & 31;
    const int m0   = blockIdx.x * BM;
    const int mtx  = blockIdx.y;                 // 0=Q, 1=K, 2=H
    const __half* __restrict__ Wp = g_Wh + (size_t)mtx * 256 * 128;

    const int wr = (wid >> 2) * 32;              // warp row base
    const int wc = (wid & 3) * 64;               // warp col base
    const int lr = lane >> 2;
    const int lc = lane & 3;

    // ldmatrix lane address components
    const int sel = lane >> 3;                   // 0..3
    const int rL  = (sel & 1) * 8 + (lane & 7);  // row within 16-row group
    const int cL  = (sel >> 1) * 8;              // k-offset (halves)

    const uint32_t aBase = (uint32_t)__cvta_generic_to_shared(As);
    const uint32_t bBase = (uint32_t)__cvta_generic_to_shared(Bs);
    uint32_t aAddr[2], bAddr[4];
    #pragma unroll
    for (int i = 0; i < 2; i++)
        aAddr[i] = aBase + ((wr + i * 16 + rL) * LDH + cL) * 2;
    #pragma unroll
    for (int j2 = 0; j2 < 4; j2++)
        bAddr[j2] = bBase + ((wc + j2 * 16 + rL) * LDH + cL) * 2;

    float acc[2][8][4];
    #pragma unroll
    for (int i = 0; i < 2; i++)
        #pragma unroll
        for (int j = 0; j < 8; j++)
            #pragma unroll
            for (int t = 0; t < 4; t++) acc[i][j][t] = 0.f;

    for (int kc = 0; kc < IN_DIM; kc += BKH) {
        __syncthreads();
        // fill A: 64 rows x 64 halves = 512 uint4; 2 per thread
        #pragma unroll
        for (int i = tid; i < 512; i += 256) {
            const int row = i >> 3;
            const int seg = (i & 7) * 8;
            const int grow = m0 + row;
            uint4 v = make_uint4(0u, 0u, 0u, 0u);
            if (grow < n) v = *(const uint4*)(g_xh + (size_t)grow * 128 + kc + seg);
            *(uint4*)&As[row * LDH + seg] = v;
        }
        // fill B: 256 rows x 64 halves = 2048 uint4; 8 per thread
        #pragma unroll
        for (int i = tid; i < 2048; i += 256) {
            const int row = i >> 3;
            const int seg = (i & 7) * 8;
            *(uint4*)&Bs[row * LDH + seg] = *(const uint4*)(Wp + (size_t)row * 128 + kc + seg);
        }
        __syncthreads();

        #pragma unroll
        for (int ks = 0; ks < 4; ks++) {
            const uint32_t ko = ks * 32;         // 16 halves = 32 bytes
            uint32_t a[2][4];
            ldm4(a[0], aAddr[0] + ko);
            ldm4(a[1], aAddr[1] + ko);
            #pragma unroll
            for (int j2 = 0; j2 < 4; j2++) {
                uint32_t b[4];
                ldm4(b, bAddr[j2] + ko);
                mma_f16(acc[0][2 * j2],     a[0], b[0], b[2]);
                mma_f16(acc[1][2 * j2],     a[1], b[0], b[2]);
                mma_f16(acc[0][2 * j2 + 1], a[0], b[1], b[3]);
                mma_f16(acc[1][2 * j2 + 1], a[1], b[1], b[3]);
            }
        }
    }

    // epilogue: Q -> fp32 + leaky; K -> fp16 + leaky; H -> fp16 + bias
    #pragma unroll
    for (int i = 0; i < 2; i++) {
        const int r0 = m0 + wr + i * 16 + lr;
        const int r1 = r0 + 8;
        #pragma unroll
        for (int j = 0; j < 8; j++) {
            const int col = wc + j * 8 + lc * 2;
            float2 v0 = make_float2(acc[i][j][0], acc[i][j][1]);
            float2 v1 = make_float2(acc[i][j][2], acc[i][j][3]);
            if (mtx < 2) {
                v0.x = v0.x > 0.f ? v0.x : NEG * v0.x;
                v0.y = v0.y > 0.f ? v0.y : NEG * v0.y;
                v1.x = v1.x > 0.f ? v1.x : NEG * v1.x;
                v1.y = v1.y > 0.f ? v1.y : NEG * v1.y;
            } else {
                const float bx = bh[col], by = bh[col + 1];
                v0.x += bx; v0.y += by;
                v1.x += bx; v1.y += by;
            }
            if (mtx == 0) {
                if (r0 < n) *(float2*)(g_Qr + (size_t)r0 * 256 + col) = v0;
                if (r1 < n) *(float2*)(g_Qr + (size_t)r1 * 256 + col) = v1;
            } else {
                __half* __restrict__ dsth = (mtx == 1) ? g_Kh : g_Hh;
                if (r0 < n) *(__half2*)(dsth + (size_t)r0 * 256 + col) = __floats2half2_rn(v0.x, v0.y);
                if (r1 < n) *(__half2*)(dsth + (size_t)r1 * 256 + col) = __floats2half2_rn(v1.x, v1.y);
            }
        }
    }
}

// ---------------- CSR build ----------------
__global__ void gat_zero(int n) {
    int i = blockIdx.x * blockDim.x + threadIdx.x;
    if (i < n) g_deg[i] = 0;
}

// block-local exclusive scan (1024 thr); writes local prefix + block total
__global__ void gat_scan1(int n) {
    __shared__ int warpsum[32];
    const int tid  = threadIdx.x;
    const int lane = tid & 31;
    const int wid  = tid >> 5;
    const int i = blockIdx.x * 1024 + tid;
    const int v = (i < n) ? g_deg[i] : 0;
    int s = v;
    #pragma unroll
    for (int off = 1; off < 32; off <<= 1) {
        int t = __shfl_up_sync(0xFFFFFFFFu, s, off);
        if (lane >= off) s += t;
    }
    if (lane == 31) warpsum[wid] = s;
    __syncthreads();
    if (wid == 0) {
        int w = warpsum[lane];
        #pragma unroll
        for (int off = 1; off < 32; off <<= 1) {
            int t = __shfl_up_sync(0xFFFFFFFFu, w, off);
            if (lane >= off) w += t;
        }
        warpsum[lane] = w;
    }
    __syncthreads();
    const int wbase = (wid == 0) ? 0 : warpsum[wid - 1];
    if (i < n) g_rowptr[i] = wbase + s - v;       // block-local exclusive
    if (tid == 1023) g_bsum[blockIdx.x] = warpsum[31];
}

// scan the block sums (nb <= 128), write exclusive offsets + grand total
__global__ void gat_scan2(int nb, int n) {
    const int tid  = threadIdx.x;   // 128 threads
    const int lane = tid & 31;
    const int wid  = tid >> 5;
    __shared__ int warpsum[4];
    const int v = (tid < nb) ? g_bsum[tid] : 0;
    int s = v;
    #pragma unroll
    for (int off = 1; off < 32; off <<= 1) {
        int t = __shfl_up_sync(0xFFFFFFFFu, s, off);
        if (lane >= off) s += t;
    }
    if (lane == 31) warpsum[wid] = s;
    __syncthreads();
    int wbase = 0;
    #pragma unroll
    for (int w = 0; w < 4; w++) if (w < wid) wbase += warpsum[w];
    if (tid < nb) g_boff[tid] = wbase + s - v;
    if (tid == 127) g_rowptr[n] = wbase + s;
}

// apply block offsets, init cursor
__global__ void gat_scan3(int n) {
    const int i = blockIdx.x * blockDim.x + threadIdx.x;
    if (i < n) {
        const int r = g_rowptr[i] + g_boff[blockIdx.x >> 2];   // 256 thr * 4 blocks = 1024
        g_rowptr[i] = r;
        g_cursor[i] = r;
    }
}

__global__ void gat_scatter(const void* __restrict__ ei, int E) {
    int e = blockIdx.x * blockDim.x + threadIdx.x;
    if (e < E) {
        int r = load_idx(ei, e);
        int c = load_idx(ei, E + e);
        int p = atomicAdd(&g_cursor[r], 1);
        g_ecol[p] = c;
    }
}

// ---------------- score pass (warp per node): e + zinv ----------------
// K row = 512 bytes fp16. lane l loads uint4 (8 halves) at byte offset l*16.
// head h = l>>3, slot t = l&7 covers dims t*8..t*8+7.
__global__ __launch_bounds__(256) void gat_score(int n) {
    const int warp = (blockIdx.x * blockDim.x + threadIdx.x) >> 5;
    const int lane = threadIdx.x & 31;
    if (warp >= n) return;
    const int u = warp;
    const int h = lane >> 3;
    const int t = lane & 7;
    const int p0 = g_rowptr[u], p1 = g_rowptr[u + 1];

    float qv[8];
    {
        const float4* qp = (const float4*)(g_Qr + (size_t)u * 256 + h * 64 + t * 8);
        float4 a = qp[0], b = qp[1];
        qv[0] = a.x; qv[1] = a.y; qv[2] = a.z; qv[3] = a.w;
        qv[4] = b.x; qv[5] = b.y; qv[6] = b.z; qv[7] = b.w;
    }

    float z = 0.f;
    for (int p = p0; p < p1; p++) {
        const int v = g_ecol[p];
        const uint4 kv = *(const uint4*)((const char*)g_Kh + (size_t)v * 512 + lane * 16);
        const float2 k0 = __half22float2(*(const __half2*)&kv.x);
        const float2 k1 = __half22float2(*(const __half2*)&kv.y);
        const float2 k2 = __half22float2(*(const __half2*)&kv.z);
        const float2 k3 = __half22float2(*(const __half2*)&kv.w);
        float s = qv[0] * k0.x + qv[1] * k0.y + qv[2] * k1.x + qv[3] * k1.y
                + qv[4] * k2.x + qv[5] * k2.y + qv[6] * k3.x + qv[7] * k3.y;
        s += __shfl_xor_sync(0xFFFFFFFFu, s, 4);
        s += __shfl_xor_sync(0xFFFFFFFFu, s, 2);
        s += __shfl_xor_sync(0xFFFFFFFFu, s, 1);
        const float e = __expf(s * 0.125f);
        z += e;
        if (t == 0) g_e[4 * (size_t)p + h] = e;
    }
    if (t == 0) g_zinv[4 * (size_t)u + h] = 1.0f / (z + EPSV);
}

// ---------------- aggregate pass (warp per node), fp16 H ----------------
// lane l handles out dims 2l, 2l+1: head h at half2 index h*32 + l of the row.
__global__ __launch_bounds__(256) void gat_aggr(float* __restrict__ out, int n) {
    const int warp = (blockIdx.x * blockDim.x + threadIdx.x) >> 5;
    const int lane = threadIdx.x & 31;
    if (warp >= n) return;
    const int u = warp;
    const int p0 = g_rowptr[u], p1 = g_rowptr[u + 1];

    const float4 zv = *(const float4*)(g_zinv + 4 * (size_t)u);
    const float i0 = zv.x, i1 = zv.y, i2 = zv.z, i3 = zv.w;

    float ax = 0.f, ay = 0.f;
    for (int p = p0; p < p1; p++) {
        const int v = g_ecol[p];
        const float4 ev = *(const float4*)(g_e + 4 * (size_t)p);
        const float a0 = ev.x * i0, a1 = ev.y * i1, a2 = ev.z * i2, a3 = ev.w * i3;
        const __half2* __restrict__ hb = (const __half2*)g_Hh + (size_t)v * 128 + lane;
        const float2 h0 = __half22float2(hb[0]);
        const float2 h1 = __half22float2(hb[32]);
        const float2 h2 = __half22float2(hb[64]);
        const float2 h3 = __half22float2(hb[96]);
        ax += a0 * h0.x + a1 * h1.x + a2 * h2.x + a3 * h3.x;
        ay += a0 * h0.y + a1 * h1.y + a2 * h2.y + a3 * h3.y;
    }
    *(float2*)(out + (size_t)u * 64 + lane * 2) = make_float2(ax * 0.25f, ay * 0.25f);
}

// ---------------- launch ----------------
extern "C" void kernel_launch(void* const* d_in, const int* in_sizes, int n_in,
                              void* d_out, int out_size) {
    const float* x  = (const float*)d_in[0];
    const void*  ei = d_in[1];
    const float* Wq = (const float*)d_in[2];
    const float* Wk = (const float*)d_in[3];
    const float* Wh = (const float*)d_in[4];
    const float* bh = (const float*)d_in[5];
    float* out = (float*)d_out;

    const int n = in_sizes[0] / IN_DIM;
    const int E = in_sizes[1] / 2;
    const int nb = (n + 1023) / 1024;

    gat_detect<<<1, 32>>>(ei, E);
    gat_xh<<<(n * 64 + 255) / 256, 256>>>(x, n * 64);
    gat_wh<<<3, 256>>>(Wq, Wk, Wh);
    gat_zero<<<(n + 255) / 256, 256>>>(n);

    dim3 gg((n + BM - 1) / BM, 4);      // y<3: GEMM Q/K/H; y==3: deg count
    gat_gemm<<<gg, 256>>>(bh, ei, E, n);

    gat_scan1<<<nb, 1024>>>(n);
    gat_scan2<<<1, 128>>>(nb, n);
    gat_scan3<<<nb * 4, 256>>>(n);
    gat_scatter<<<(E + 255) / 256, 256>>>(ei, E);

    const int nblocks = (n * 32 + 255) / 256;
    gat_score<<<nblocks, 256>>>(n);
    gat_aggr<<<nblocks, 256>>>(out, n);
}